// round 10
// baseline (speedup 1.0000x reference)
#include <cuda_runtime.h>
#include <math.h>
#include <stdint.h>

#define NE    16
#define NB    512
#define NI    10
#define NF    3
#define NPROJ 7
#define NEMB  32
#define NROWS 78
#define NT    256
#define NEB   (NE*NB)        // 8192
#define NCELL (NE*NB*NI)     // 81920
#define CHUNK 8
#define TPB   256
#define NEBL  27
#define BUFW  (CHUNK*TPB*NF) // 6144 floats per x buffer
#define S36   36

#define INV_SQRT_DEG 0.7071067811865476f

// dynamic smem (floats):
// [0..432)              sCoef (persists)
// [448..448+12288)      sx double buffer
//    buf0 overlay during prologue: sH1 [0..972), sEff [1024..3211)
// [12736..12736+5128)   dedicated prologue scratch
#define SCR_OFF   12736
#define SMEM_FLOATS (SCR_OFF + 5128)   // 17864 floats = 71456 B

__device__ __forceinline__ float gelu_exact(float x) {
    return 0.5f * x * (1.0f + erff(x * 0.7071067811865476f));
}

__device__ __forceinline__ void cp_async16(uint32_t saddr, const void* gaddr) {
    asm volatile("cp.async.cg.shared.global [%0], [%1], 16;\n"
                 :: "r"(saddr), "l"(gaddr));
}
__device__ __forceinline__ void cp_commit() {
    asm volatile("cp.async.commit_group;\n" ::: "memory");
}
template<int N>
__device__ __forceinline__ void cp_wait() {
    asm volatile("cp.async.wait_group %0;\n" :: "n"(N) : "memory");
}

// occ is grid-limited at 2.16 blocks/SM — the occ-3 register cap (80) was
// pure downside (prologue spills). Bound 2 -> 128-reg cap, no spills.
__global__ void __launch_bounds__(TPB, 2) fused_kernel(
    const float* __restrict__ x,
    const float* __restrict__ h0,
    const float* __restrict__ emb,
    const float* __restrict__ w0, const float* __restrict__ w1,
    const float* __restrict__ b0, const float* __restrict__ b1,
    const float* __restrict__ wn, const float* __restrict__ bn,
    const float* __restrict__ damping,
    const float* __restrict__ hW_in, const float* __restrict__ hb_in,
    const float* __restrict__ hW_out, const float* __restrict__ hb_out,
    float* __restrict__ out)
{
    extern __shared__ float sm[];
    float* sCoef = sm;                    // 432
    float* sx    = sm + 448;              // 12288
    float* sH1   = sx;                    // 972   (buf0 overlay)
    float* sEff  = sx + 1024;             // 2187  (buf0 overlay)
    float* scr   = sm + SCR_OFF;
    float* sWin  = scr;                   // 32*36
    float* sWout = scr + 1152;            // 78*36
    float* sEmb  = scr + 3960;            // 27*36
    float* sBin  = scr + 4932;            // 32
    float* sBo   = scr + 4964;            // 78
    float* sBase = scr + 5044;            // 78

    const int tid  = threadIdx.x;
    const int blk  = blockIdx.x;
    const int e    = blk / 20;
    const int eb0  = (blk * TPB) / NI;
    const int cell = blk * TPB + tid;

    const float* gx = x + (size_t)blk * TPB * NF;
    const uint32_t sbase = (uint32_t)__cvta_generic_to_shared(sx);

    auto fill_chunk = [&](int c, int buf) {
        const uint32_t dbase = sbase + (uint32_t)buf * (BUFW * 4);
        #pragma unroll
        for (int k = 0; k < 6; k++) {
            const int q   = tid + k * TPB;        // 0..1535
            const int tt  = q / 192;
            const int rem = q - tt * 192;
            const float* src = gx + (size_t)(c * CHUNK + tt) * ((size_t)NCELL * NF)
                                  + rem * 4;
            cp_async16(dbase + (uint32_t)(tt * 3072 + rem * 16), src);
        }
        cp_commit();
    };

    // chunk 0 streams into buf1 while the prologue computes
    fill_chunk(0, 1);

    // ================= PROLOGUE: staging (coalesced) =================
    for (int idx = tid; idx < NEMB*NEMB; idx += TPB)
        sWin[(idx >> 5) * S36 + (idx & 31)] = hW_in[e*NEMB*NEMB + idx];
    for (int idx = tid; idx < NROWS*NEMB; idx += TPB)
        sWout[(idx >> 5) * S36 + (idx & 31)] = hW_out[e*79*NEMB + idx];
    {
        const int gmax = NEB * NEMB - 1;
        for (int idx = tid; idx < NEBL*NEMB; idx += TPB) {
            int g = eb0 * NEMB + idx;
            if (g > gmax) g = gmax;
            sEmb[(idx >> 5) * S36 + (idx & 31)] = emb[g];
        }
    }
    if (tid < NEMB)  sBin[tid] = hb_in[e*NEMB + tid];
    if (tid < NROWS) sBo[tid]  = hb_out[e*79 + tid];
    if (tid < 28) {
        sBase[tid]      = w0[e*28 + tid];
        sBase[28 + tid] = w1[e*28 + tid];
    }
    if (tid < NPROJ) {
        sBase[56 + tid] = b0[e*NPROJ + tid];
        sBase[63 + tid] = b1[e*NPROJ + tid];
        sBase[70 + tid] = wn[e*NPROJ + tid];
    }
    if (tid == 0) sBase[77] = bn[e];
    __syncthreads();

    const int  ebl  = tid >> 3;
    const int  part = tid & 7;
    const bool act  = (tid < NEBL * 8);
    const unsigned lane  = tid & 31;
    const unsigned gmask = 0xFFu << (lane & ~7u);

    // ---- h1: rows o = part + 8j, float4 operands from smem ----
    if (act) {
        const float4* erow = (const float4*)&sEmb[ebl * S36];
        float hseg[4];
        #pragma unroll
        for (int j = 0; j < 4; j++) {
            const int o = part + 8*j;
            float a = sBin[o];
            const float4* wrow = (const float4*)&sWin[o * S36];
            #pragma unroll
            for (int t = 0; t < 8; t++) {
                const float4 wv = wrow[t];
                const float4 ev = erow[t];
                a = fmaf(wv.x, ev.x, a);
                a = fmaf(wv.y, ev.y, a);
                a = fmaf(wv.z, ev.z, a);
                a = fmaf(wv.w, ev.w, a);
            }
            hseg[j] = gelu_exact(a);
        }
        #pragma unroll
        for (int j = 0; j < 4; j++)
            sH1[ebl * S36 + part + 8*j] = hseg[j];
    }
    __syncwarp();

    if (act) {
        // h1 row cached in registers (now actually registers)
        float h1r[NEMB];
        {
            const float4* hrow = (const float4*)&sH1[ebl * S36];
            #pragma unroll
            for (int t = 0; t < 8; t++) {
                const float4 hv = hrow[t];
                h1r[4*t]   = hv.x; h1r[4*t+1] = hv.y;
                h1r[4*t+2] = hv.z; h1r[4*t+3] = hv.w;
            }
        }

        float r[10];
        float n0 = 0.f, n1 = 0.f, n2 = 0.f, n3 = 0.f, n4 = 0.f, n5 = 0.f;
        #pragma unroll
        for (int k = 0; k < 10; k++) {
            const int o = part + 8*k;
            if (o < NROWS) {
                float a = sBo[o];
                const float4* wr = (const float4*)&sWout[o * S36];
                #pragma unroll
                for (int t = 0; t < 8; t++) {
                    const float4 wv = wr[t];
                    a = fmaf(wv.x, h1r[4*t],   a);
                    a = fmaf(wv.y, h1r[4*t+1], a);
                    a = fmaf(wv.z, h1r[4*t+2], a);
                    a = fmaf(wv.w, h1r[4*t+3], a);
                }
                r[k] = a;
                const float a2 = a * a;
                if      (o < 28) n0 += a2;
                else if (o < 56) n1 += a2;
                else if (o < 63) n2 += a2;
                else if (o < 70) n3 += a2;
                else if (o < 77) n4 += a2;
                else             n5 += a2;
            } else r[k] = 0.0f;
        }
        #pragma unroll
        for (int d = 1; d <= 4; d <<= 1) {
            n0 += __shfl_xor_sync(gmask, n0, d);
            n1 += __shfl_xor_sync(gmask, n1, d);
            n2 += __shfl_xor_sync(gmask, n2, d);
            n3 += __shfl_xor_sync(gmask, n3, d);
            n4 += __shfl_xor_sync(gmask, n4, d);
            n5 += __shfl_xor_sync(gmask, n5, d);
        }

        float rn0 = 0.f, rn1 = 0.f, rn2 = 0.f, rn3 = 0.f, rn4 = 0.f;
        #pragma unroll
        for (int i = 0; i < 28; i++) { rn0 = fmaf(sBase[i], sBase[i], rn0);
                                       rn1 = fmaf(sBase[28+i], sBase[28+i], rn1); }
        #pragma unroll
        for (int i = 0; i < NPROJ; i++) { rn2 = fmaf(sBase[56+i], sBase[56+i], rn2);
                                          rn3 = fmaf(sBase[63+i], sBase[63+i], rn3);
                                          rn4 = fmaf(sBase[70+i], sBase[70+i], rn4); }
        const float rn5 = sBase[77] * sBase[77];

        auto scale_of = [](float rn, float on) {
            const float mx = fmaxf(sqrtf(rn) * 0.5f, 0.01f);
            return fminf(mx / (sqrtf(on) + 1e-8f), 1.0f);
        };
        const float s0 = scale_of(rn0, n0), s1 = scale_of(rn1, n1);
        const float s2 = scale_of(rn2, n2), s3 = scale_of(rn3, n3);
        const float s4 = scale_of(rn4, n4), s5 = scale_of(rn5, n5);

        float* sE = sEff + ebl * 81;
        #pragma unroll
        for (int k = 0; k < 10; k++) {
            const int o = part + 8*k;
            if (o < NROWS) {
                float sc;
                if      (o < 28) sc = s0;
                else if (o < 56) sc = s1;
                else if (o < 63) sc = s2;
                else if (o < 70) sc = s3;
                else if (o < 77) sc = s4;
                else             sc = s5;
                sE[o] = sBase[o] + r[k] * sc;
            }
        }
        __syncwarp(gmask);

        if (part == 0) {
            float Q[16];
            #pragma unroll
            for (int i = 0; i < 16; i++) Q[i] = 0.0f;
            float v[4] = {0.f, 0.f, 0.f, 0.f};
            float cst = sE[77];

            #pragma unroll
            for (int p = 0; p < NPROJ; p++) {
                const float wnp = sE[70 + p] * INV_SQRT_DEG;
                const float g2 = sE[56 + p], g3 = sE[63 + p];
                #pragma unroll
                for (int i = 0; i < 4; i++) {
                    const float g0i = sE[4*p + i];
                    const float g1i = sE[28 + 4*p + i];
                    const float tq = wnp * g0i;
                    #pragma unroll
                    for (int k = 0; k < 4; k++)
                        Q[i*4 + k] = fmaf(tq, sE[28 + 4*p + k], Q[i*4 + k]);
                    v[i] = fmaf(wnp * g2, g1i, fmaf(wnp * g3, g0i, v[i]));
                }
                cst = fmaf(wnp * g2, g3, cst);
            }

            const float omd = 1.0f - 1.0f / (1.0f + expf(-damping[e]));

            float* oc = sCoef + ebl * 16;
            oc[0]  = cst;
            oc[1]  = v[0];
            oc[2]  = v[1];
            oc[3]  = v[2];
            oc[4]  = v[3] + omd;
            oc[5]  = Q[0];
            oc[6]  = Q[5];
            oc[7]  = Q[10];
            oc[8]  = Q[1] + Q[4];
            oc[9]  = Q[2] + Q[8];
            oc[10] = Q[6] + Q[9];
            oc[11] = Q[3] + Q[12];
            oc[12] = Q[7] + Q[13];
            oc[13] = Q[11] + Q[14];
            oc[14] = Q[15];
            oc[15] = 0.0f;
        }
    }
    __syncthreads();   // prologue done; buf0 free

    // ================= per-thread coefficients =================
    const int myl = cell / NI - eb0;
    const float* oc = sCoef + myl * 16;
    const float Cc  = oc[0];
    const float V0  = oc[1],  V1  = oc[2],  V2  = oc[3];
    const float Uc  = oc[4];
    const float A00 = oc[5],  A11 = oc[6],  A22 = oc[7];
    const float A01 = oc[8],  A02 = oc[9],  A12 = oc[10];
    const float B0  = oc[11], B1  = oc[12], B2  = oc[13];
    const float S33 = oc[14];

    float h = h0[cell];
    float* op = out + cell;
    const int xoff = 3 * tid;

    // ================= recurrent scan; chunk 0 is in buf 1 =================
    const int NCHUNK = NT / CHUNK;   // 32
    for (int c = 0; c < NCHUNK; c++) {
        const int buf = (c & 1) ^ 1;      // c=0 -> buf1
        if (c + 1 < NCHUNK) {
            fill_chunk(c + 1, buf ^ 1);
            cp_wait<1>();
        } else {
            cp_wait<0>();
        }
        __syncthreads();

        const float* sb = sx + buf * BUFW;
        #pragma unroll
        for (int tt = 0; tt < CHUNK; tt++) {
            const float x0 = sb[tt * (TPB*NF) + xoff];
            const float x1 = sb[tt * (TPB*NF) + xoff + 1];
            const float x2 = sb[tt * (TPB*NF) + xoff + 2];

            const float q0 = fmaf(A02, x2, fmaf(A01, x1, fmaf(A00, x0, V0)));
            const float q1 = fmaf(A12, x2, fmaf(A11, x1, V1));
            const float q2 = fmaf(A22, x2, V2);
            const float g  = fmaf(q2, x2, fmaf(q1, x1, fmaf(q0, x0, Cc)));
            const float u  = fmaf(B2, x2, fmaf(B1, x1, fmaf(B0, x0, Uc)));
            h = fmaf(h, fmaf(S33, h, u), g);

            *op = h;
            op += NCELL;
        }
        __syncthreads();
    }
}

extern "C" void kernel_launch(void* const* d_in, const int* in_sizes, int n_in,
                              void* d_out, int out_size)
{
    const float* inputs    = (const float*)d_in[0];
    const float* h0        = (const float*)d_in[1];
    const float* embedding = (const float*)d_in[2];
    const float* w0        = (const float*)d_in[3];
    const float* w1        = (const float*)d_in[4];
    const float* b0        = (const float*)d_in[5];
    const float* b1        = (const float*)d_in[6];
    const float* wn        = (const float*)d_in[7];
    const float* bn        = (const float*)d_in[8];
    const float* damping   = (const float*)d_in[9];
    const float* hW_in     = (const float*)d_in[10];
    const float* hb_in     = (const float*)d_in[11];
    const float* hW_out    = (const float*)d_in[12];
    const float* hb_out    = (const float*)d_in[13];
    float* out = (float*)d_out;

    const int smem_bytes = SMEM_FLOATS * 4;   // 71456
    cudaFuncSetAttribute(fused_kernel,
                         cudaFuncAttributeMaxDynamicSharedMemorySize, smem_bytes);

    fused_kernel<<<NCELL/TPB, TPB, smem_bytes>>>(
        inputs, h0, embedding, w0, w1, b0, b1, wn, bn, damping,
        hW_in, hb_in, hW_out, hb_out, out);
}

// round 11
// speedup vs baseline: 1.3569x; 1.3569x over previous
#include <cuda_runtime.h>
#include <math.h>
#include <stdint.h>

#define NE    16
#define NB    512
#define NI    10
#define NF    3
#define NPROJ 7
#define NEMB  32
#define NROWS 78
#define NT    256
#define NEB   (NE*NB)        // 8192
#define NCELL (NE*NB*NI)     // 81920
#define CHUNK 8
#define TPB   320
#define GRID  (NCELL/TPB)    // 256 blocks <= 296 occ-2 slots -> single wave
#define NEBL  32             // ebs per block, exact (320/10 = 32)
#define SEGW  (TPB*NF)       // 960 floats per timestep segment
#define BUFW  (CHUNK*SEGW)   // 7680 floats per x buffer
#define S36   36

#define INV_SQRT_DEG 0.7071067811865476f

// dynamic smem (floats):
// [0..512)            sCoef 32*16 (persists)
// [512..512+15360)    sx double buffer (2 x 7680)
//    prologue overlay in buf0: sH1 [0..1152), sEff [1152..3744)
// [15872..21184)      prologue scratch:
//    sWin 1152 | sWout 2808 | sEmb 1152 | sBin 32 | sBo 78 | sBase 80
#define SX_OFF    512
#define SCR_OFF   (SX_OFF + 2*BUFW)          // 15872
#define SMEM_FLOATS (SCR_OFF + 5312)         // 21184 floats = 84736 B

__device__ __forceinline__ float gelu_exact(float x) {
    return 0.5f * x * (1.0f + erff(x * 0.7071067811865476f));
}

__device__ __forceinline__ void cp_async16(uint32_t saddr, const void* gaddr) {
    asm volatile("cp.async.cg.shared.global [%0], [%1], 16;\n"
                 :: "r"(saddr), "l"(gaddr));
}
__device__ __forceinline__ void cp_commit() {
    asm volatile("cp.async.commit_group;\n" ::: "memory");
}
template<int N>
__device__ __forceinline__ void cp_wait() {
    asm volatile("cp.async.wait_group %0;\n" :: "n"(N) : "memory");
}

__global__ void __launch_bounds__(TPB, 2) fused_kernel(
    const float* __restrict__ x,
    const float* __restrict__ h0,
    const float* __restrict__ emb,
    const float* __restrict__ w0, const float* __restrict__ w1,
    const float* __restrict__ b0, const float* __restrict__ b1,
    const float* __restrict__ wn, const float* __restrict__ bn,
    const float* __restrict__ damping,
    const float* __restrict__ hW_in, const float* __restrict__ hb_in,
    const float* __restrict__ hW_out, const float* __restrict__ hb_out,
    float* __restrict__ out)
{
    extern __shared__ float sm[];
    float* sCoef = sm;                    // 512
    float* sx    = sm + SX_OFF;           // 15360
    float* sH1   = sx;                    // 1152  (buf0 overlay)
    float* sEff  = sx + 1152;             // 2592  (buf0 overlay; ends 3744 < 7680)
    float* scr   = sm + SCR_OFF;
    float* sWin  = scr;                   // 32*36 = 1152
    float* sWout = scr + 1152;            // 78*36 = 2808
    float* sEmb  = scr + 3960;            // 32*36 = 1152
    float* sBin  = scr + 5112;            // 32
    float* sBo   = scr + 5144;            // 78
    float* sBase = scr + 5224;            // 78

    const int tid  = threadIdx.x;
    const int blk  = blockIdx.x;
    const int e    = blk / 16;            // 16 blocks per ensemble (256/16)
    const int eb0  = blk * NEBL;          // exact block->eb alignment
    const int cell = blk * TPB + tid;

    const float* gx = x + (size_t)blk * TPB * NF;
    const uint32_t sbase = (uint32_t)__cvta_generic_to_shared(sx);

    auto fill_chunk = [&](int c, int buf) {
        const uint32_t dbase = sbase + (uint32_t)buf * (BUFW * 4);
        #pragma unroll
        for (int k = 0; k < 6; k++) {
            const int q   = tid + k * TPB;        // 0..1919
            const int tt  = q / 240;              // 240 x16B per segment
            const int rem = q - tt * 240;
            const float* src = gx + (size_t)(c * CHUNK + tt) * ((size_t)NCELL * NF)
                                  + rem * 4;
            cp_async16(dbase + (uint32_t)(tt * (SEGW*4) + rem * 16), src);
        }
        cp_commit();
    };

    // chunk 0 streams into buf1 while the prologue computes
    fill_chunk(0, 1);

    // ================= PROLOGUE: staging (coalesced) =================
    for (int idx = tid; idx < NEMB*NEMB; idx += TPB)
        sWin[(idx >> 5) * S36 + (idx & 31)] = hW_in[e*NEMB*NEMB + idx];
    for (int idx = tid; idx < NROWS*NEMB; idx += TPB)
        sWout[(idx >> 5) * S36 + (idx & 31)] = hW_out[e*79*NEMB + idx];
    for (int idx = tid; idx < NEBL*NEMB; idx += TPB)
        sEmb[(idx >> 5) * S36 + (idx & 31)] = emb[(size_t)eb0 * NEMB + idx];
    if (tid < NEMB)  sBin[tid] = hb_in[e*NEMB + tid];
    if (tid < NROWS) sBo[tid]  = hb_out[e*79 + tid];
    if (tid < 28) {
        sBase[tid]      = w0[e*28 + tid];
        sBase[28 + tid] = w1[e*28 + tid];
    }
    if (tid < NPROJ) {
        sBase[56 + tid] = b0[e*NPROJ + tid];
        sBase[63 + tid] = b1[e*NPROJ + tid];
        sBase[70 + tid] = wn[e*NPROJ + tid];
    }
    if (tid == 0) sBase[77] = bn[e];
    __syncthreads();

    const int  ebl  = tid >> 3;           // 0..39, active 0..31
    const int  part = tid & 7;
    const bool act  = (tid < NEBL * 8);   // 256 of 320 threads
    const unsigned lane  = tid & 31;
    const unsigned gmask = 0xFFu << (lane & ~7u);

    // ---- h1: rows o = part + 8j ----
    if (act) {
        const float4* erow = (const float4*)&sEmb[ebl * S36];
        float hseg[4];
        #pragma unroll
        for (int j = 0; j < 4; j++) {
            const int o = part + 8*j;
            float a = sBin[o];
            const float4* wrow = (const float4*)&sWin[o * S36];
            #pragma unroll
            for (int t = 0; t < 8; t++) {
                const float4 wv = wrow[t];
                const float4 ev = erow[t];
                a = fmaf(wv.x, ev.x, a);
                a = fmaf(wv.y, ev.y, a);
                a = fmaf(wv.z, ev.z, a);
                a = fmaf(wv.w, ev.w, a);
            }
            hseg[j] = gelu_exact(a);
        }
        #pragma unroll
        for (int j = 0; j < 4; j++)
            sH1[ebl * S36 + part + 8*j] = hseg[j];
    }
    __syncwarp();

    if (act) {
        float h1r[NEMB];
        {
            const float4* hrow = (const float4*)&sH1[ebl * S36];
            #pragma unroll
            for (int t = 0; t < 8; t++) {
                const float4 hv = hrow[t];
                h1r[4*t]   = hv.x; h1r[4*t+1] = hv.y;
                h1r[4*t+2] = hv.z; h1r[4*t+3] = hv.w;
            }
        }

        float r[10];
        float n0 = 0.f, n1 = 0.f, n2 = 0.f, n3 = 0.f, n4 = 0.f, n5 = 0.f;
        #pragma unroll
        for (int k = 0; k < 10; k++) {
            const int o = part + 8*k;
            if (o < NROWS) {
                float a = sBo[o];
                const float4* wr = (const float4*)&sWout[o * S36];
                #pragma unroll
                for (int t = 0; t < 8; t++) {
                    const float4 wv = wr[t];
                    a = fmaf(wv.x, h1r[4*t],   a);
                    a = fmaf(wv.y, h1r[4*t+1], a);
                    a = fmaf(wv.z, h1r[4*t+2], a);
                    a = fmaf(wv.w, h1r[4*t+3], a);
                }
                r[k] = a;
                const float a2 = a * a;
                if      (o < 28) n0 += a2;
                else if (o < 56) n1 += a2;
                else if (o < 63) n2 += a2;
                else if (o < 70) n3 += a2;
                else if (o < 77) n4 += a2;
                else             n5 += a2;
            } else r[k] = 0.0f;
        }
        #pragma unroll
        for (int d = 1; d <= 4; d <<= 1) {
            n0 += __shfl_xor_sync(gmask, n0, d);
            n1 += __shfl_xor_sync(gmask, n1, d);
            n2 += __shfl_xor_sync(gmask, n2, d);
            n3 += __shfl_xor_sync(gmask, n3, d);
            n4 += __shfl_xor_sync(gmask, n4, d);
            n5 += __shfl_xor_sync(gmask, n5, d);
        }

        float rn0 = 0.f, rn1 = 0.f, rn2 = 0.f, rn3 = 0.f, rn4 = 0.f;
        #pragma unroll
        for (int i = 0; i < 28; i++) { rn0 = fmaf(sBase[i], sBase[i], rn0);
                                       rn1 = fmaf(sBase[28+i], sBase[28+i], rn1); }
        #pragma unroll
        for (int i = 0; i < NPROJ; i++) { rn2 = fmaf(sBase[56+i], sBase[56+i], rn2);
                                          rn3 = fmaf(sBase[63+i], sBase[63+i], rn3);
                                          rn4 = fmaf(sBase[70+i], sBase[70+i], rn4); }
        const float rn5 = sBase[77] * sBase[77];

        auto scale_of = [](float rn, float on) {
            const float mx = fmaxf(sqrtf(rn) * 0.5f, 0.01f);
            return fminf(mx / (sqrtf(on) + 1e-8f), 1.0f);
        };
        const float s0 = scale_of(rn0, n0), s1 = scale_of(rn1, n1);
        const float s2 = scale_of(rn2, n2), s3 = scale_of(rn3, n3);
        const float s4 = scale_of(rn4, n4), s5 = scale_of(rn5, n5);

        float* sE = sEff + ebl * 81;
        #pragma unroll
        for (int k = 0; k < 10; k++) {
            const int o = part + 8*k;
            if (o < NROWS) {
                float sc;
                if      (o < 28) sc = s0;
                else if (o < 56) sc = s1;
                else if (o < 63) sc = s2;
                else if (o < 70) sc = s3;
                else if (o < 77) sc = s4;
                else             sc = s5;
                sE[o] = sBase[o] + r[k] * sc;
            }
        }
        __syncwarp(gmask);

        if (part == 0) {
            float Q[16];
            #pragma unroll
            for (int i = 0; i < 16; i++) Q[i] = 0.0f;
            float v[4] = {0.f, 0.f, 0.f, 0.f};
            float cst = sE[77];

            #pragma unroll
            for (int p = 0; p < NPROJ; p++) {
                const float wnp = sE[70 + p] * INV_SQRT_DEG;
                const float g2 = sE[56 + p], g3 = sE[63 + p];
                #pragma unroll
                for (int i = 0; i < 4; i++) {
                    const float g0i = sE[4*p + i];
                    const float g1i = sE[28 + 4*p + i];
                    const float tq = wnp * g0i;
                    #pragma unroll
                    for (int k = 0; k < 4; k++)
                        Q[i*4 + k] = fmaf(tq, sE[28 + 4*p + k], Q[i*4 + k]);
                    v[i] = fmaf(wnp * g2, g1i, fmaf(wnp * g3, g0i, v[i]));
                }
                cst = fmaf(wnp * g2, g3, cst);
            }

            const float omd = 1.0f - 1.0f / (1.0f + expf(-damping[e]));

            float* oc = sCoef + ebl * 16;
            oc[0]  = cst;
            oc[1]  = v[0];
            oc[2]  = v[1];
            oc[3]  = v[2];
            oc[4]  = v[3] + omd;
            oc[5]  = Q[0];
            oc[6]  = Q[5];
            oc[7]  = Q[10];
            oc[8]  = Q[1] + Q[4];
            oc[9]  = Q[2] + Q[8];
            oc[10] = Q[6] + Q[9];
            oc[11] = Q[3] + Q[12];
            oc[12] = Q[7] + Q[13];
            oc[13] = Q[11] + Q[14];
            oc[14] = Q[15];
            oc[15] = 0.0f;
        }
    }
    __syncthreads();   // prologue done; buf0 free

    // ================= per-thread coefficients =================
    const int myl = tid / NI;             // 0..31, exact
    const float* oc = sCoef + myl * 16;
    const float Cc  = oc[0];
    const float V0  = oc[1],  V1  = oc[2],  V2  = oc[3];
    const float Uc  = oc[4];
    const float A00 = oc[5],  A11 = oc[6],  A22 = oc[7];
    const float A01 = oc[8],  A02 = oc[9],  A12 = oc[10];
    const float B0  = oc[11], B1  = oc[12], B2  = oc[13];
    const float S33 = oc[14];

    float h = h0[cell];
    float* op = out + cell;
    const int xoff = 3 * tid;

    // ================= recurrent scan; chunk 0 is in buf 1 =================
    const int NCHUNK = NT / CHUNK;   // 32
    for (int c = 0; c < NCHUNK; c++) {
        const int buf = (c & 1) ^ 1;      // c=0 -> buf1
        if (c + 1 < NCHUNK) {
            fill_chunk(c + 1, buf ^ 1);
            cp_wait<1>();
        } else {
            cp_wait<0>();
        }
        __syncthreads();

        const float* sb = sx + buf * BUFW;
        #pragma unroll
        for (int tt = 0; tt < CHUNK; tt++) {
            const float x0 = sb[tt * SEGW + xoff];
            const float x1 = sb[tt * SEGW + xoff + 1];
            const float x2 = sb[tt * SEGW + xoff + 2];

            const float q0 = fmaf(A02, x2, fmaf(A01, x1, fmaf(A00, x0, V0)));
            const float q1 = fmaf(A12, x2, fmaf(A11, x1, V1));
            const float q2 = fmaf(A22, x2, V2);
            const float g  = fmaf(q2, x2, fmaf(q1, x1, fmaf(q0, x0, Cc)));
            const float u  = fmaf(B2, x2, fmaf(B1, x1, fmaf(B0, x0, Uc)));
            h = fmaf(h, fmaf(S33, h, u), g);

            *op = h;
            op += NCELL;
        }
        __syncthreads();
    }
}

extern "C" void kernel_launch(void* const* d_in, const int* in_sizes, int n_in,
                              void* d_out, int out_size)
{
    const float* inputs    = (const float*)d_in[0];
    const float* h0        = (const float*)d_in[1];
    const float* embedding = (const float*)d_in[2];
    const float* w0        = (const float*)d_in[3];
    const float* w1        = (const float*)d_in[4];
    const float* b0        = (const float*)d_in[5];
    const float* b1        = (const float*)d_in[6];
    const float* wn        = (const float*)d_in[7];
    const float* bn        = (const float*)d_in[8];
    const float* damping   = (const float*)d_in[9];
    const float* hW_in     = (const float*)d_in[10];
    const float* hb_in     = (const float*)d_in[11];
    const float* hW_out    = (const float*)d_in[12];
    const float* hb_out    = (const float*)d_in[13];
    float* out = (float*)d_out;

    const int smem_bytes = SMEM_FLOATS * 4;   // 84736
    cudaFuncSetAttribute(fused_kernel,
                         cudaFuncAttributeMaxDynamicSharedMemorySize, smem_bytes);

    fused_kernel<<<GRID, TPB, smem_bytes>>>(
        inputs, h0, embedding, w0, w1, b0, b1, wn, bn, damping,
        hW_in, hb_in, hW_out, hb_out, out);
}